// round 8
// baseline (speedup 1.0000x reference)
#include <cuda_runtime.h>
#include <cuda_bf16.h>
#include <math.h>
#include <stdint.h>

#define NB 8
#define NS 1025
#define NE 1408
#define NH 16
#define ND 88
#define NM (NB*NS)      // 8200
#define DPAD 96
#define QKROW (NH*DPAD) // 1536
#define SVT 1088        // padded token dim for V^T (17*64)
#define EE  (NE*NE)

// Persistent scratch (__device__ globals zero-initialized; padding regions
// never written -> stay zero, used as MMA zero-padding).
static __device__ __nv_bfloat16 g_ah[(size_t)NM * NE];
static __device__ __nv_bfloat16 g_al[(size_t)NM * NE];
static __device__ __nv_bfloat16 g_wh[(size_t)4 * EE];
static __device__ __nv_bfloat16 g_wl[(size_t)4 * EE];
static __device__ __nv_bfloat16 g_ch[(size_t)NM * NE];
static __device__ __nv_bfloat16 g_cl[(size_t)NM * NE];
static __device__ __nv_bfloat16 g_qh[(size_t)NM * QKROW];
static __device__ __nv_bfloat16 g_ql[(size_t)NM * QKROW];
static __device__ __nv_bfloat16 g_kh[(size_t)NM * QKROW];
static __device__ __nv_bfloat16 g_kl[(size_t)NM * QKROW];
static __device__ __nv_bfloat16 g_vth[(size_t)NB * NH * DPAD * SVT];
static __device__ __nv_bfloat16 g_vtl[(size_t)NB * NH * DPAD * SVT];

// ===========================================================================
// Helpers
// ===========================================================================
__device__ __forceinline__ uint32_t smem_to_u32(const void* p) {
    uint32_t a;
    asm("{ .reg .u64 t; cvta.to.shared.u64 t, %1; cvt.u32.u64 %0, t; }"
        : "=r"(a) : "l"(p));
    return a;
}
__device__ __forceinline__ void ldsm_x4(uint32_t* r, uint32_t addr) {
    asm volatile("ldmatrix.sync.aligned.m8n8.x4.shared.b16 {%0,%1,%2,%3}, [%4];"
                 : "=r"(r[0]), "=r"(r[1]), "=r"(r[2]), "=r"(r[3]) : "r"(addr));
}
__device__ __forceinline__ void mma_bf16(float* c, const uint32_t* a,
                                         const uint32_t* b) {
    asm volatile(
        "mma.sync.aligned.m16n8k16.row.col.f32.bf16.bf16.f32 "
        "{%0,%1,%2,%3}, {%4,%5,%6,%7}, {%8,%9}, {%0,%1,%2,%3};"
        : "+f"(c[0]), "+f"(c[1]), "+f"(c[2]), "+f"(c[3])
        : "r"(a[0]), "r"(a[1]), "r"(a[2]), "r"(a[3]), "r"(b[0]), "r"(b[1]));
}
__device__ __forceinline__ void cp16(uint32_t dst, const void* src) {
    asm volatile("cp.async.cg.shared.global [%0], [%1], 16;"
                 :: "r"(dst), "l"(__cvta_generic_to_global(src)));
}
#define CP_COMMIT() asm volatile("cp.async.commit_group;" ::: "memory")
#define CP_WAIT(n)  asm volatile("cp.async.wait_group %0;" :: "n"(n) : "memory")

__device__ __forceinline__ void bsplit(float x, __nv_bfloat16& h, __nv_bfloat16& l) {
    h = __float2bfloat16(x);
    l = __float2bfloat16(x - __bfloat162float(h));
}

// ===========================================================================
// Prep: split fp32 -> bf16 hi/lo
// ===========================================================================
__global__ void split_kernel(const float* __restrict__ in,
                             __nv_bfloat16* __restrict__ hi,
                             __nv_bfloat16* __restrict__ lo, int n4)
{
    int i = blockIdx.x * blockDim.x + threadIdx.x;
    if (i >= n4) return;
    float4 x = ((const float4*)in)[i];
    union { __nv_bfloat162 h2[2]; uint2 u; } H, L;
    __nv_bfloat162 h0 = __float22bfloat162_rn(make_float2(x.x, x.y));
    float2 f0 = __bfloat1622float2(h0);
    H.h2[0] = h0;
    L.h2[0] = __float22bfloat162_rn(make_float2(x.x - f0.x, x.y - f0.y));
    __nv_bfloat162 h1 = __float22bfloat162_rn(make_float2(x.z, x.w));
    float2 f1 = __bfloat1622float2(h1);
    H.h2[1] = h1;
    L.h2[1] = __float22bfloat162_rn(make_float2(x.z - f1.x, x.w - f1.y));
    ((uint2*)hi)[i] = H.u;
    ((uint2*)lo)[i] = L.u;
}

// ===========================================================================
// HMMA GEMM, split bf16 inputs (3 terms): C = A*W^T + bias
// CTA 128x128, 4 warps (2x2), warp tile 64x64, BK=32, cp.async 2-stage.
// ldsm:MMA ratio 1:6.
// MODE 0: fp32 out.  MODE 1: RoPE + bf16 hi/lo to padded [m][1536].
// MODE 2: bf16 hi/lo transposed to [b,h,96,1088].
// ===========================================================================
#define GK      NE
#define BKC     32
#define NCHUNK  (GK / BKC)    // 44
#define SROW    40
#define SROWB   (SROW * 2)
#define MAT_BYTES   (128 * SROWB)          // 10240
#define STAGE_BYTES (4 * MAT_BYTES)        // 40960
#define GEMM_SMEM   (2 * STAGE_BYTES)      // 81920

template<int MODE>
__global__ __launch_bounds__(128) void gemm_hmma_kernel(
    const __nv_bfloat16* __restrict__ Ah, const __nv_bfloat16* __restrict__ Al,
    const __nv_bfloat16* __restrict__ Wh, const __nv_bfloat16* __restrict__ Wl,
    const float* __restrict__ bias, float* __restrict__ C,
    __nv_bfloat16* __restrict__ Oh, __nv_bfloat16* __restrict__ Ol,
    const float* __restrict__ rcos, const float* __restrict__ rsin, int M)
{
    extern __shared__ char sm[];
    const uint32_t smemu = smem_to_u32(sm);
    const int tid  = threadIdx.x;
    const int wid  = tid >> 5;
    const int lane = tid & 31;
    const int bm = blockIdx.y * 128;
    const int bn = blockIdx.x * 128;
    const int wm = (wid >> 1) * 64;     // 0 / 64
    const int wn = (wid & 1) * 64;      // 0 / 64

    // cp.async slots: per matrix 512 x 16B, 128 threads -> 4 slots each
    int rowL[4], chL[4], gaL[4];
#pragma unroll
    for (int i = 0; i < 4; i++) {
        int slot = tid + i * 128;
        rowL[i] = slot >> 2;
        chL[i]  = slot & 3;
        int ga = bm + rowL[i];
        gaL[i] = (ga < M) ? ga : (M - 1);
    }

    const uint32_t aoff =
        (uint32_t)((wm + ((lane >> 3) & 1) * 8 + (lane & 7)) * SROWB
                   + (lane >> 4) * 16);
    const uint32_t boff =
        (uint32_t)((wn + ((lane >> 4) << 3) + (lane & 7)) * SROWB
                   + ((lane >> 3) & 1) * 16);

    float acc[4][8][4];
#pragma unroll
    for (int mi = 0; mi < 4; mi++)
#pragma unroll
        for (int nt = 0; nt < 8; nt++)
#pragma unroll
            for (int j = 0; j < 4; j++) acc[mi][nt][j] = 0.f;

#define GEMM_LOAD(c_) do { \
    const int k0_ = (c_) * BKC; \
    const uint32_t sb_ = smemu + ((c_) & 1) * STAGE_BYTES; \
    _Pragma("unroll") \
    for (int i_ = 0; i_ < 4; i_++) { \
        uint32_t so_ = (uint32_t)(rowL[i_] * SROWB + chL[i_] * 16); \
        size_t ao_ = ((size_t)gaL[i_] * GK + k0_ + chL[i_] * 8) * 2; \
        cp16(sb_ + so_,                 (const char*)Ah + ao_); \
        cp16(sb_ + MAT_BYTES + so_,     (const char*)Al + ao_); \
        size_t bo_ = ((size_t)(bn + rowL[i_]) * GK + k0_ + chL[i_] * 8) * 2; \
        cp16(sb_ + 2 * MAT_BYTES + so_, (const char*)Wh + bo_); \
        cp16(sb_ + 3 * MAT_BYTES + so_, (const char*)Wl + bo_); \
    } \
} while (0)

    GEMM_LOAD(0);
    CP_COMMIT();

#pragma unroll 1
    for (int c = 0; c < NCHUNK; c++) {
        if (c + 1 < NCHUNK) {
            GEMM_LOAD(c + 1);
            CP_COMMIT();
            CP_WAIT(1);
        } else {
            CP_WAIT(0);
        }
        __syncthreads();

        const uint32_t base = smemu + (uint32_t)((c & 1) * STAGE_BYTES);
        const uint32_t aHi = base;
        const uint32_t aLo = base + MAT_BYTES;
        const uint32_t bHi = base + 2 * MAT_BYTES;
        const uint32_t bLo = base + 3 * MAT_BYTES;
#pragma unroll
        for (int ks = 0; ks < 2; ks++) {
            const uint32_t ksb = ks * 32;
            uint32_t ah[16], al[16], bh[16], bl[16];
#pragma unroll
            for (int mi = 0; mi < 4; mi++) {
                ldsm_x4(&ah[mi * 4], aHi + aoff + mi * 16 * SROWB + ksb);
                ldsm_x4(&al[mi * 4], aLo + aoff + mi * 16 * SROWB + ksb);
            }
#pragma unroll
            for (int j = 0; j < 4; j++) {
                ldsm_x4(&bh[j * 4], bHi + boff + j * 16 * SROWB + ksb);
                ldsm_x4(&bl[j * 4], bLo + boff + j * 16 * SROWB + ksb);
            }
#pragma unroll
            for (int mi = 0; mi < 4; mi++)
#pragma unroll
                for (int nt = 0; nt < 8; nt++) {
                    mma_bf16(acc[mi][nt], &ah[mi * 4], &bh[nt * 2]);
                    mma_bf16(acc[mi][nt], &ah[mi * 4], &bl[nt * 2]);
                    mma_bf16(acc[mi][nt], &al[mi * 4], &bh[nt * 2]);
                }
        }
        __syncthreads();
    }

    // ---- epilogue ----
    const int r0 = bm + wm + (lane >> 2);
    const int c0 = bn + wn + (lane & 3) * 2;
#pragma unroll
    for (int mi = 0; mi < 4; mi++) {
#pragma unroll
        for (int nt = 0; nt < 8; nt++) {
            const int gc = c0 + nt * 8;
            const float bx = bias[gc], by = bias[gc + 1];
            const int hh = gc / ND;
            const int dd = gc - hh * ND;
#pragma unroll
            for (int half = 0; half < 2; half++) {
                const int gr = r0 + mi * 16 + half * 8;
                if (gr >= M) continue;
                float xr = acc[mi][nt][2 * half + 0] + bx;
                float xi = acc[mi][nt][2 * half + 1] + by;
                if (MODE == 0) {
                    *(float2*)(C + (size_t)gr * NE + gc) = make_float2(xr, xi);
                } else if (MODE == 1) {
                    const int st = gr % NS;
                    const float cc = rcos[st * (ND / 2) + (dd >> 1)];
                    const float ss = rsin[st * (ND / 2) + (dd >> 1)];
                    float orr = xr * cc - xi * ss;
                    float oii = xr * ss + xi * cc;
                    __nv_bfloat16 h0, l0, h1, l1;
                    bsplit(orr, h0, l0);
                    bsplit(oii, h1, l1);
                    size_t off = (size_t)gr * QKROW + hh * DPAD + dd;
                    *(__nv_bfloat162*)(Oh + off) = __halves2bfloat162(h0, h1);
                    *(__nv_bfloat162*)(Ol + off) = __halves2bfloat162(l0, l1);
                } else {
                    const int bb = gr / NS;
                    const int st = gr - bb * NS;
                    size_t base2 = ((size_t)((bb * NH + hh) * DPAD) + dd) * SVT + st;
                    __nv_bfloat16 h0, l0, h1, l1;
                    bsplit(xr, h0, l0);
                    bsplit(xi, h1, l1);
                    Oh[base2]       = h0;
                    Ol[base2]       = l0;
                    Oh[base2 + SVT] = h1;
                    Ol[base2 + SVT] = l1;
                }
            }
        }
    }
}

// ===========================================================================
// HMMA flash attention, split bf16 (3 terms both GEMMs).
// BQ=64, BK=64, 4 warps. K double-buffered (prefetch kt+1), V wait deferred
// to after softmax. Epilogue writes ctx as bf16 hi/lo for the Wo GEMM.
// ===========================================================================
#define KSTB 208
#define VSTB 144
#define KBUF_B 13312                 // 64 * KSTB
#define OFF_K0H 0
#define OFF_K0L (KBUF_B)
#define OFF_K1H (2 * KBUF_B)
#define OFF_K1L (3 * KBUF_B)
#define OFF_VH  (4 * KBUF_B)         // 53248
#define OFF_VL  (OFF_VH + 96 * VSTB) // 67072
#define OFF_PH  (OFF_VL + 96 * VSTB) // 80896
#define OFF_PL  (OFF_PH + 64 * VSTB) // 90112
#define ATT_SMEM (OFF_PL + 64 * VSTB) // 99328

__global__ __launch_bounds__(128) void attn_hmma_kernel()
{
    extern __shared__ char sm[];
    const uint32_t smemu = smem_to_u32(sm);
    const int tid  = threadIdx.x;
    const int wid  = tid >> 5;
    const int lane = tid & 31;
    const int wm   = wid * 16;

    const int qt = blockIdx.x, h = blockIdx.y, b = blockIdx.z;
    const int q0 = qt * 64;

    const char* qh_base = (const char*)(g_qh + (size_t)b * NS * QKROW + h * DPAD);
    const char* ql_base = (const char*)(g_ql + (size_t)b * NS * QKROW + h * DPAD);
    const char* kh_base = (const char*)(g_kh + (size_t)b * NS * QKROW + h * DPAD);
    const char* kl_base = (const char*)(g_kl + (size_t)b * NS * QKROW + h * DPAD);
    const char* vh_base = (const char*)(g_vth + (size_t)(b * NH + h) * DPAD * SVT);
    const char* vl_base = (const char*)(g_vtl + (size_t)(b * NH + h) * DPAD * SVT);

    // ---- stage Q via K buffer 0, build register fragments ----
    for (int i = tid; i < 768; i += 128) {
        int row = i / 12, ch = i % 12;
        int tok = q0 + row; if (tok > NS - 1) tok = NS - 1;
        size_t gb = (size_t)tok * (QKROW * 2) + ch * 16;
        cp16(smemu + OFF_K0H + row * KSTB + ch * 16, qh_base + gb);
        cp16(smemu + OFF_K0L + row * KSTB + ch * 16, ql_base + gb);
    }
    CP_COMMIT(); CP_WAIT(0);
    __syncthreads();

    const uint32_t aoffQ = (uint32_t)((wm + ((lane >> 3) & 1) * 8 + (lane & 7)) * KSTB
                                      + (lane >> 4) * 16);
    uint32_t qhf[6][4], qlf[6][4];
#pragma unroll
    for (int ks = 0; ks < 6; ks++) {
        ldsm_x4(qhf[ks], smemu + OFF_K0H + aoffQ + ks * 32);
        ldsm_x4(qlf[ks], smemu + OFF_K0L + aoffQ + ks * 32);
    }
    __syncthreads();

    // ---- preload K(0) into buffer 0 ----
    for (int i = tid; i < 768; i += 128) {
        int rk = i / 12, ck = i % 12;
        int tok = rk; if (tok > NS - 1) tok = NS - 1;
        size_t gk = (size_t)tok * (QKROW * 2) + ck * 16;
        cp16(smemu + OFF_K0H + rk * KSTB + ck * 16, kh_base + gk);
        cp16(smemu + OFF_K0L + rk * KSTB + ck * 16, kl_base + gk);
    }
    CP_COMMIT();

    float acc_o[11][4];
#pragma unroll
    for (int nt = 0; nt < 11; nt++)
#pragma unroll
        for (int j = 0; j < 4; j++) acc_o[nt][j] = 0.f;
    float mrun[2] = {-INFINITY, -INFINITY};
    float lrun[2] = {0.f, 0.f};

    const float scale = 0.10660035817780521f;
    const uint32_t kboff = (uint32_t)((((lane >> 4) << 3) + (lane & 7)) * KSTB
                                      + ((lane >> 3) & 1) * 16);
    const uint32_t vboff = (uint32_t)((((lane >> 4) << 3) + (lane & 7)) * VSTB
                                      + ((lane >> 3) & 1) * 16);
    const uint32_t apoff = (uint32_t)((wm + ((lane >> 3) & 1) * 8 + (lane & 7)) * VSTB
                                      + (lane >> 4) * 16);
    const int colb = (lane & 3) * 2;
    const int prow_lo = wm + (lane >> 2);

#pragma unroll 1
    for (int kt = 0; kt < 17; kt++) {
        const int k0 = kt * 64;
        const uint32_t kcur = smemu + ((kt & 1) ? OFF_K1H : OFF_K0H);
        const uint32_t kcurL = kcur + KBUF_B;

        // issue V(kt)
        for (int i = tid; i < 768; i += 128) {
            int rv = i / 8, cv = i % 8;
            size_t gv = (size_t)rv * (SVT * 2) + k0 * 2 + cv * 16;
            cp16(smemu + OFF_VH + rv * VSTB + cv * 16, vh_base + gv);
            cp16(smemu + OFF_VL + rv * VSTB + cv * 16, vl_base + gv);
        }
        CP_COMMIT();
        // issue K(kt+1) into other buffer
        if (kt < 16) {
            const uint32_t knxt = smemu + (((kt + 1) & 1) ? OFF_K1H : OFF_K0H);
            const int kn0 = (kt + 1) * 64;
            for (int i = tid; i < 768; i += 128) {
                int rk = i / 12, ck = i % 12;
                int tok = kn0 + rk; if (tok > NS - 1) tok = NS - 1;
                size_t gk = (size_t)tok * (QKROW * 2) + ck * 16;
                cp16(knxt + rk * KSTB + ck * 16, kh_base + gk);
                cp16(knxt + KBUF_B + rk * KSTB + ck * 16, kl_base + gk);
            }
            CP_COMMIT();
            CP_WAIT(2);     // K(kt) complete
        } else {
            CP_WAIT(1);     // K(16) complete
        }
        __syncthreads();

        // ---- S = Q K^T ----
        float sacc[8][4];
#pragma unroll
        for (int nt = 0; nt < 8; nt++)
#pragma unroll
            for (int j = 0; j < 4; j++) sacc[nt][j] = 0.f;

#pragma unroll
        for (int ks = 0; ks < 6; ks++) {
            uint32_t kbh[16], kbl[16];
#pragma unroll
            for (int j = 0; j < 4; j++) {
                ldsm_x4(&kbh[j * 4], kcur  + kboff + j * 16 * KSTB + ks * 32);
                ldsm_x4(&kbl[j * 4], kcurL + kboff + j * 16 * KSTB + ks * 32);
            }
#pragma unroll
            for (int nt = 0; nt < 8; nt++) {
                mma_bf16(sacc[nt], qhf[ks], &kbh[nt * 2]);
                mma_bf16(sacc[nt], qhf[ks], &kbl[nt * 2]);
                mma_bf16(sacc[nt], qlf[ks], &kbh[nt * 2]);
            }
        }

#pragma unroll
        for (int nt = 0; nt < 8; nt++)
#pragma unroll
            for (int j = 0; j < 4; j++) sacc[nt][j] *= scale;
        if (k0 + 64 > NS) {
#pragma unroll
            for (int nt = 0; nt < 8; nt++)
#pragma unroll
                for (int j = 0; j < 4; j++) {
                    int col = k0 + nt * 8 + colb + (j & 1);
                    if (col >= NS) sacc[nt][j] = -INFINITY;
                }
        }

        // ---- online softmax ----
        float ml0 = -INFINITY, ml1 = -INFINITY;
#pragma unroll
        for (int nt = 0; nt < 8; nt++) {
            ml0 = fmaxf(ml0, fmaxf(sacc[nt][0], sacc[nt][1]));
            ml1 = fmaxf(ml1, fmaxf(sacc[nt][2], sacc[nt][3]));
        }
        ml0 = fmaxf(ml0, __shfl_xor_sync(0xffffffffu, ml0, 1));
        ml0 = fmaxf(ml0, __shfl_xor_sync(0xffffffffu, ml0, 2));
        ml1 = fmaxf(ml1, __shfl_xor_sync(0xffffffffu, ml1, 1));
        ml1 = fmaxf(ml1, __shfl_xor_sync(0xffffffffu, ml1, 2));

        float mn0 = fmaxf(mrun[0], ml0), mn1 = fmaxf(mrun[1], ml1);
        float al0 = __expf(mrun[0] - mn0), al1 = __expf(mrun[1] - mn1);
        mrun[0] = mn0; mrun[1] = mn1;

        float rs0 = 0.f, rs1 = 0.f;
#pragma unroll
        for (int nt = 0; nt < 8; nt++) {
            float p00 = __expf(sacc[nt][0] - mn0);
            float p01 = __expf(sacc[nt][1] - mn0);
            float p10 = __expf(sacc[nt][2] - mn1);
            float p11 = __expf(sacc[nt][3] - mn1);
            rs0 += p00 + p01;
            rs1 += p10 + p11;
            __nv_bfloat16 h0, l0, h1, l1;
            bsplit(p00, h0, l0); bsplit(p01, h1, l1);
            uint32_t po = (uint32_t)(prow_lo * VSTB + (nt * 8 + colb) * 2);
            *(__nv_bfloat162*)(sm + OFF_PH + po) = __halves2bfloat162(h0, h1);
            *(__nv_bfloat162*)(sm + OFF_PL + po) = __halves2bfloat162(l0, l1);
            bsplit(p10, h0, l0); bsplit(p11, h1, l1);
            uint32_t po2 = po + 8 * VSTB;
            *(__nv_bfloat162*)(sm + OFF_PH + po2) = __halves2bfloat162(h0, h1);
            *(__nv_bfloat162*)(sm + OFF_PL + po2) = __halves2bfloat162(l0, l1);
        }
        rs0 += __shfl_xor_sync(0xffffffffu, rs0, 1);
        rs0 += __shfl_xor_sync(0xffffffffu, rs0, 2);
        rs1 += __shfl_xor_sync(0xffffffffu, rs1, 1);
        rs1 += __shfl_xor_sync(0xffffffffu, rs1, 2);
        lrun[0] = lrun[0] * al0 + rs0;
        lrun[1] = lrun[1] * al1 + rs1;

#pragma unroll
        for (int nt = 0; nt < 11; nt++) {
            acc_o[nt][0] *= al0; acc_o[nt][1] *= al0;
            acc_o[nt][2] *= al1; acc_o[nt][3] *= al1;
        }

        // V(kt) must be complete and visible before PV
        if (kt < 16) CP_WAIT(1); else CP_WAIT(0);
        __syncthreads();

        // ---- O += P V ----
#pragma unroll
        for (int ks = 0; ks < 4; ks++) {
            uint32_t aph[4], apl[4];
            ldsm_x4(aph, smemu + OFF_PH + apoff + ks * 32);
            ldsm_x4(apl, smemu + OFF_PL + apoff + ks * 32);
            uint32_t vbh[24], vbl[24];
#pragma unroll
            for (int j = 0; j < 6; j++) {
                ldsm_x4(&vbh[j * 4], smemu + OFF_VH + vboff + j * 16 * VSTB + ks * 32);
                ldsm_x4(&vbl[j * 4], smemu + OFF_VL + vboff + j * 16 * VSTB + ks * 32);
            }
#pragma unroll
            for (int nt = 0; nt < 11; nt++) {
                mma_bf16(acc_o[nt], aph, &vbh[nt * 2]);
                mma_bf16(acc_o[nt], aph, &vbl[nt * 2]);
                mma_bf16(acc_o[nt], apl, &vbh[nt * 2]);
            }
        }
        __syncthreads();   // protect V & P buffers for next iteration
    }

    // ---- epilogue: ctx as bf16 hi/lo (feeds Wo GEMM directly) ----
    const float inv0 = 1.f / lrun[0];
    const float inv1 = 1.f / lrun[1];
    const int gq0 = q0 + wm + (lane >> 2);
    const int gq1 = gq0 + 8;
    const size_t ob = (size_t)b * NS * NE + (size_t)h * ND;
#pragma unroll
    for (int nt = 0; nt < 11; nt++) {
        int col = nt * 8 + colb;
        __nv_bfloat16 h0, l0, h1, l1;
        if (gq0 < NS) {
            bsplit(acc_o[nt][0] * inv0, h0, l0);
            bsplit(acc_o[nt][1] * inv0, h1, l1);
            size_t off = ob + (size_t)gq0 * NE + col;
            *(__nv_bfloat162*)(g_ch + off) = __halves2bfloat162(h0, h1);
            *(__nv_bfloat162*)(g_cl + off) = __halves2bfloat162(l0, l1);
        }
        if (gq1 < NS) {
            bsplit(acc_o[nt][2] * inv1, h0, l0);
            bsplit(acc_o[nt][3] * inv1, h1, l1);
            size_t off = ob + (size_t)gq1 * NE + col;
            *(__nv_bfloat162*)(g_ch + off) = __halves2bfloat162(h0, h1);
            *(__nv_bfloat162*)(g_cl + off) = __halves2bfloat162(l0, l1);
        }
    }
}

// ---------------------------------------------------------------------------
// Launch
// ---------------------------------------------------------------------------
extern "C" void kernel_launch(void* const* d_in, const int* in_sizes, int n_in,
                              void* d_out, int out_size)
{
    const float* hidden = (const float*)d_in[0];
    const float* fcos   = (const float*)d_in[1];
    const float* fsin   = (const float*)d_in[2];
    const float* Wq     = (const float*)d_in[3];
    const float* bq     = (const float*)d_in[4];
    const float* Wk     = (const float*)d_in[5];
    const float* bk     = (const float*)d_in[6];
    const float* Wv     = (const float*)d_in[7];
    const float* bv     = (const float*)d_in[8];
    const float* Wo     = (const float*)d_in[9];
    const float* bo     = (const float*)d_in[10];
    float* out = (float*)d_out;

    __nv_bfloat16 *ah, *al, *wh, *wl, *ch, *cl, *qh, *ql, *kh, *kl, *vth, *vtl;
    cudaGetSymbolAddress((void**)&ah,  g_ah);
    cudaGetSymbolAddress((void**)&al,  g_al);
    cudaGetSymbolAddress((void**)&wh,  g_wh);
    cudaGetSymbolAddress((void**)&wl,  g_wl);
    cudaGetSymbolAddress((void**)&ch,  g_ch);
    cudaGetSymbolAddress((void**)&cl,  g_cl);
    cudaGetSymbolAddress((void**)&qh,  g_qh);
    cudaGetSymbolAddress((void**)&ql,  g_ql);
    cudaGetSymbolAddress((void**)&kh,  g_kh);
    cudaGetSymbolAddress((void**)&kl,  g_kl);
    cudaGetSymbolAddress((void**)&vth, g_vth);
    cudaGetSymbolAddress((void**)&vtl, g_vtl);

    static int smem_set = 0;
    if (!smem_set) {
        cudaFuncSetAttribute(gemm_hmma_kernel<0>,
                             cudaFuncAttributeMaxDynamicSharedMemorySize, GEMM_SMEM);
        cudaFuncSetAttribute(gemm_hmma_kernel<1>,
                             cudaFuncAttributeMaxDynamicSharedMemorySize, GEMM_SMEM);
        cudaFuncSetAttribute(gemm_hmma_kernel<2>,
                             cudaFuncAttributeMaxDynamicSharedMemorySize, GEMM_SMEM);
        cudaFuncSetAttribute(attn_hmma_kernel,
                             cudaFuncAttributeMaxDynamicSharedMemorySize, ATT_SMEM);
        smem_set = 1;
    }

    // ---- prep: split fp32 -> bf16 hi/lo ----
    const int nA4 = NM * NE / 4;
    const int nW4 = EE / 4;
    split_kernel<<<(nA4 + 255) / 256, 256>>>(hidden, ah, al, nA4);
    split_kernel<<<(nW4 + 255) / 256, 256>>>(Wq, wh + 0 * (size_t)EE, wl + 0 * (size_t)EE, nW4);
    split_kernel<<<(nW4 + 255) / 256, 256>>>(Wk, wh + 1 * (size_t)EE, wl + 1 * (size_t)EE, nW4);
    split_kernel<<<(nW4 + 255) / 256, 256>>>(Wv, wh + 2 * (size_t)EE, wl + 2 * (size_t)EE, nW4);
    split_kernel<<<(nW4 + 255) / 256, 256>>>(Wo, wh + 3 * (size_t)EE, wl + 3 * (size_t)EE, nW4);

    dim3 gemm_grid(NE / 128, (NM + 127) / 128);  // (11, 65)

    gemm_hmma_kernel<1><<<gemm_grid, 128, GEMM_SMEM>>>(
        ah, al, wh + 0 * (size_t)EE, wl + 0 * (size_t)EE, bq, nullptr,
        qh, ql, fcos, fsin, NM);
    gemm_hmma_kernel<1><<<gemm_grid, 128, GEMM_SMEM>>>(
        ah, al, wh + 1 * (size_t)EE, wl + 1 * (size_t)EE, bk, nullptr,
        kh, kl, fcos, fsin, NM);
    gemm_hmma_kernel<2><<<gemm_grid, 128, GEMM_SMEM>>>(
        ah, al, wh + 2 * (size_t)EE, wl + 2 * (size_t)EE, bv, nullptr,
        vth, vtl, nullptr, nullptr, NM);

    dim3 attn_grid(17, NH, NB);
    attn_hmma_kernel<<<attn_grid, 128, ATT_SMEM>>>();

    gemm_hmma_kernel<0><<<gemm_grid, 128, GEMM_SMEM>>>(
        ch, cl, wh + 3 * (size_t)EE, wl + 3 * (size_t)EE, bo, out,
        nullptr, nullptr, nullptr, nullptr, NM);
}

// round 9
// speedup vs baseline: 1.5156x; 1.5156x over previous
#include <cuda_runtime.h>
#include <cuda_fp16.h>
#include <math.h>
#include <stdint.h>

#define NB 8
#define NS 1025
#define NE 1408
#define NH 16
#define ND 88
#define NM (NB*NS)      // 8200
#define DPAD 96
#define QKROW (NH*DPAD) // 1536
#define SVT 1088        // padded token dim for V^T
#define EE  (NE*NE)

// Persistent scratch (zero-initialized; padding regions stay zero).
static __device__ __half g_ah[(size_t)NM * NE];          // hidden, fp16 hi only
static __device__ __half g_wh[(size_t)4 * EE];
static __device__ __half g_wl[(size_t)4 * EE];
static __device__ __half g_ch[(size_t)NM * NE];          // ctx, hi only
static __device__ __half g_qh[(size_t)NM * QKROW];       // q, hi only
static __device__ __half g_kh[(size_t)NM * QKROW];
static __device__ __half g_kl[(size_t)NM * QKROW];
static __device__ __half g_vth[(size_t)NB * NH * DPAD * SVT];
static __device__ __half g_vtl[(size_t)NB * NH * DPAD * SVT];

// ===========================================================================
// Helpers
// ===========================================================================
__device__ __forceinline__ uint32_t smem_to_u32(const void* p) {
    uint32_t a;
    asm("{ .reg .u64 t; cvta.to.shared.u64 t, %1; cvt.u32.u64 %0, t; }"
        : "=r"(a) : "l"(p));
    return a;
}
__device__ __forceinline__ void ldsm_x4(uint32_t* r, uint32_t addr) {
    asm volatile("ldmatrix.sync.aligned.m8n8.x4.shared.b16 {%0,%1,%2,%3}, [%4];"
                 : "=r"(r[0]), "=r"(r[1]), "=r"(r[2]), "=r"(r[3]) : "r"(addr));
}
__device__ __forceinline__ void mma_f16(float* c, const uint32_t* a,
                                        const uint32_t* b) {
    asm volatile(
        "mma.sync.aligned.m16n8k16.row.col.f32.f16.f16.f32 "
        "{%0,%1,%2,%3}, {%4,%5,%6,%7}, {%8,%9}, {%0,%1,%2,%3};"
        : "+f"(c[0]), "+f"(c[1]), "+f"(c[2]), "+f"(c[3])
        : "r"(a[0]), "r"(a[1]), "r"(a[2]), "r"(a[3]), "r"(b[0]), "r"(b[1]));
}
__device__ __forceinline__ void cp16(uint32_t dst, const void* src) {
    asm volatile("cp.async.cg.shared.global [%0], [%1], 16;"
                 :: "r"(dst), "l"(__cvta_generic_to_global(src)));
}
#define CP_COMMIT() asm volatile("cp.async.commit_group;" ::: "memory")
#define CP_WAIT(n)  asm volatile("cp.async.wait_group %0;" :: "n"(n) : "memory")

__device__ __forceinline__ void hsplit(float x, __half& h, __half& l) {
    h = __float2half_rn(x);
    l = __float2half_rn(x - __half2float(h));
}

// ===========================================================================
// Prep kernels
// ===========================================================================
__global__ void tohalf_kernel(const float* __restrict__ in,
                              __half* __restrict__ hi, int n4)
{
    int i = blockIdx.x * blockDim.x + threadIdx.x;
    if (i >= n4) return;
    float4 x = ((const float4*)in)[i];
    union { __half2 h2[2]; uint2 u; } H;
    H.h2[0] = __floats2half2_rn(x.x, x.y);
    H.h2[1] = __floats2half2_rn(x.z, x.w);
    ((uint2*)hi)[i] = H.u;
}

__global__ void split4_kernel(const float* __restrict__ w0,
                              const float* __restrict__ w1,
                              const float* __restrict__ w2,
                              const float* __restrict__ w3,
                              __half* __restrict__ hi,
                              __half* __restrict__ lo, int n4)
{
    int i = blockIdx.x * blockDim.x + threadIdx.x;
    if (i >= n4) return;
    const int g = blockIdx.y;
    const float* in = (g == 0) ? w0 : (g == 1) ? w1 : (g == 2) ? w2 : w3;
    size_t base4 = (size_t)g * (EE / 4) + i;
    float4 x = ((const float4*)in)[i];
    float xs[4] = {x.x, x.y, x.z, x.w};
    union { __half hh[4]; uint2 u; } H, L;
#pragma unroll
    for (int j = 0; j < 4; j++) hsplit(xs[j], H.hh[j], L.hh[j]);
    ((uint2*)hi)[base4] = H.u;
    ((uint2*)lo)[base4] = L.u;
}

// ===========================================================================
// HMMA GEMM, fp16 2-term: C = A * (Wh + Wl)^T + bias
// A fp16 (hi only) [M,K], W hi/lo [N,K]. CTA 128x128, 8 warps (2x4),
// warp tile 64x32, BK=32, cp.async 2-stage.
// Fused QKV: grid.x = 33 (g = bx/11): g0 -> Q (RoPE, hi), g1 -> K (RoPE,
// hi+lo), g2 -> V^T (hi+lo).
// ===========================================================================
#define GK      NE
#define BKC     32
#define NCHUNK  (GK / BKC)    // 44
#define SROW    40
#define SROWB   (SROW * 2)
#define MAT_BYTES   (128 * SROWB)          // 10240
#define STAGE_BYTES (3 * MAT_BYTES)        // 30720 (A, WH, WL)
#define GEMM_SMEM   (2 * STAGE_BYTES)      // 61440

#define GEMM_PROLOG \
    extern __shared__ char sm[]; \
    const uint32_t smemu = smem_to_u32(sm); \
    const int tid  = threadIdx.x; \
    const int wid  = tid >> 5; \
    const int lane = tid & 31; \
    const int bm = blockIdx.y * 128; \
    const int wm = (wid >> 2) * 64; \
    const int wn = (wid & 3) * 32; \
    int rowL[2], chL[2], gaL[2]; \
    _Pragma("unroll") \
    for (int i = 0; i < 2; i++) { \
        int slot = tid + i * 256; \
        rowL[i] = slot >> 2; \
        chL[i]  = slot & 3; \
        int ga = bm + rowL[i]; \
        gaL[i] = (ga < NM) ? ga : (NM - 1); \
    } \
    const uint32_t aoff = \
        (uint32_t)((wm + ((lane >> 3) & 1) * 8 + (lane & 7)) * SROWB \
                   + (lane >> 4) * 16); \
    const uint32_t boff = \
        (uint32_t)((wn + ((lane >> 4) << 3) + (lane & 7)) * SROWB \
                   + ((lane >> 3) & 1) * 16); \
    float acc[4][4][4]; \
    _Pragma("unroll") \
    for (int mi = 0; mi < 4; mi++) \
        _Pragma("unroll") \
        for (int ni = 0; ni < 4; ni++) \
            _Pragma("unroll") \
            for (int j = 0; j < 4; j++) acc[mi][ni][j] = 0.f;

#define GEMM_LOAD(c_) do { \
    const int k0_ = (c_) * BKC; \
    const uint32_t sb_ = smemu + ((c_) & 1) * STAGE_BYTES; \
    _Pragma("unroll") \
    for (int i_ = 0; i_ < 2; i_++) { \
        uint32_t so_ = (uint32_t)(rowL[i_] * SROWB + chL[i_] * 16); \
        size_t ao_ = ((size_t)gaL[i_] * GK + k0_ + chL[i_] * 8) * 2; \
        cp16(sb_ + so_, (const char*)Ah + ao_); \
        size_t bo_ = ((size_t)(bn + rowL[i_]) * GK + k0_ + chL[i_] * 8) * 2; \
        cp16(sb_ + MAT_BYTES + so_,     (const char*)Wh + bo_); \
        cp16(sb_ + 2 * MAT_BYTES + so_, (const char*)Wl + bo_); \
    } \
} while (0)

#define GEMM_MAINLOOP \
    GEMM_LOAD(0); \
    CP_COMMIT(); \
    _Pragma("unroll 1") \
    for (int c = 0; c < NCHUNK; c++) { \
        if (c + 1 < NCHUNK) { GEMM_LOAD(c + 1); CP_COMMIT(); CP_WAIT(1); } \
        else { CP_WAIT(0); } \
        __syncthreads(); \
        const uint32_t base = smemu + (uint32_t)((c & 1) * STAGE_BYTES); \
        const uint32_t aHi = base; \
        const uint32_t bHi = base + MAT_BYTES; \
        const uint32_t bLo = base + 2 * MAT_BYTES; \
        _Pragma("unroll") \
        for (int ks = 0; ks < 2; ks++) { \
            const uint32_t ksb = ks * 32; \
            uint32_t ah[16], bh[8], bl[8]; \
            _Pragma("unroll") \
            for (int mi = 0; mi < 4; mi++) \
                ldsm_x4(&ah[mi * 4], aHi + aoff + mi * 16 * SROWB + ksb); \
            ldsm_x4(&bh[0], bHi + boff + ksb); \
            ldsm_x4(&bh[4], bHi + boff + 16 * SROWB + ksb); \
            ldsm_x4(&bl[0], bLo + boff + ksb); \
            ldsm_x4(&bl[4], bLo + boff + 16 * SROWB + ksb); \
            _Pragma("unroll") \
            for (int mi = 0; mi < 4; mi++) \
                _Pragma("unroll") \
                for (int ni = 0; ni < 4; ni++) { \
                    mma_f16(acc[mi][ni], &ah[mi * 4], &bh[ni * 2]); \
                    mma_f16(acc[mi][ni], &ah[mi * 4], &bl[ni * 2]); \
                } \
        } \
        __syncthreads(); \
    }

// Fused QKV GEMM
__global__ __launch_bounds__(256, 2) void gemm_qkv_kernel(
    const float* __restrict__ bq, const float* __restrict__ bk,
    const float* __restrict__ bv,
    const float* __restrict__ rcos, const float* __restrict__ rsin)
{
    const int g  = blockIdx.x / 11;
    const int bn = (blockIdx.x % 11) * 128;
    const __half* Ah = g_ah;
    const __half* Wh = g_wh + (size_t)g * EE;
    const __half* Wl = g_wl + (size_t)g * EE;
    const float* bias = (g == 0) ? bq : (g == 1) ? bk : bv;

    GEMM_PROLOG
    GEMM_MAINLOOP

    const int r0 = bm + wm + (lane >> 2);
    const int c0 = bn + wn + (lane & 3) * 2;
#pragma unroll
    for (int mi = 0; mi < 4; mi++) {
#pragma unroll
        for (int nt = 0; nt < 4; nt++) {
            const int gc = c0 + nt * 8;
            const float bx = bias[gc], by = bias[gc + 1];
            const int hh = gc / ND;
            const int dd = gc - hh * ND;
#pragma unroll
            for (int half2i = 0; half2i < 2; half2i++) {
                const int gr = r0 + mi * 16 + half2i * 8;
                if (gr >= NM) continue;
                float xr = acc[mi][nt][2 * half2i + 0] + bx;
                float xi = acc[mi][nt][2 * half2i + 1] + by;
                if (g <= 1) {
                    // RoPE
                    const int st = gr % NS;
                    const float cc = rcos[st * (ND / 2) + (dd >> 1)];
                    const float ss = rsin[st * (ND / 2) + (dd >> 1)];
                    float orr = xr * cc - xi * ss;
                    float oii = xr * ss + xi * cc;
                    size_t off = (size_t)gr * QKROW + hh * DPAD + dd;
                    if (g == 0) {
                        *(__half2*)(g_qh + off) = __floats2half2_rn(orr, oii);
                    } else {
                        __half h0, l0, h1, l1;
                        hsplit(orr, h0, l0);
                        hsplit(oii, h1, l1);
                        *(__half2*)(g_kh + off) = __halves2half2(h0, h1);
                        *(__half2*)(g_kl + off) = __halves2half2(l0, l1);
                    }
                } else {
                    const int bb = gr / NS;
                    const int st = gr - bb * NS;
                    size_t base2 = ((size_t)((bb * NH + hh) * DPAD) + dd) * SVT + st;
                    __half h0, l0, h1, l1;
                    hsplit(xr, h0, l0);
                    hsplit(xi, h1, l1);
                    g_vth[base2]       = h0;
                    g_vtl[base2]       = l0;
                    g_vth[base2 + SVT] = h1;
                    g_vtl[base2 + SVT] = l1;
                }
            }
        }
    }
}

// Wo GEMM (fp32 out)
__global__ __launch_bounds__(256, 2) void gemm_wo_kernel(
    const float* __restrict__ bias, float* __restrict__ C)
{
    const int bn = blockIdx.x * 128;
    const __half* Ah = g_ch;
    const __half* Wh = g_wh + (size_t)3 * EE;
    const __half* Wl = g_wl + (size_t)3 * EE;

    GEMM_PROLOG
    GEMM_MAINLOOP

    const int r0 = bm + wm + (lane >> 2);
    const int c0 = bn + wn + (lane & 3) * 2;
#pragma unroll
    for (int mi = 0; mi < 4; mi++) {
#pragma unroll
        for (int nt = 0; nt < 4; nt++) {
            const int gc = c0 + nt * 8;
            const float bx = bias[gc], by = bias[gc + 1];
#pragma unroll
            for (int half2i = 0; half2i < 2; half2i++) {
                const int gr = r0 + mi * 16 + half2i * 8;
                if (gr >= NM) continue;
                float xr = acc[mi][nt][2 * half2i + 0] + bx;
                float xi = acc[mi][nt][2 * half2i + 1] + by;
                *(float2*)(C + (size_t)gr * NE + gc) = make_float2(xr, xi);
            }
        }
    }
}

// ===========================================================================
// HMMA flash attention, fp16 2-term.
// BQ=64, BK=64, 4 warps, 3 CTAs/SM. Q and P hi-only; K and V hi+lo.
// ===========================================================================
#define KSTB 208
#define VSTB 144
#define OFF_KH 0
#define OFF_KL 13312
#define OFF_VH 26624
#define OFF_VL 40448
#define OFF_PH 54272
#define ATT_SMEM 63488

__global__ __launch_bounds__(128, 3) void attn_hmma_kernel()
{
    extern __shared__ char sm[];
    const uint32_t smemu = smem_to_u32(sm);
    const int tid  = threadIdx.x;
    const int wid  = tid >> 5;
    const int lane = tid & 31;
    const int wm   = wid * 16;

    const int qt = blockIdx.x, h = blockIdx.y, b = blockIdx.z;
    const int q0 = qt * 64;

    const char* qh_base = (const char*)(g_qh + (size_t)b * NS * QKROW + h * DPAD);
    const char* kh_base = (const char*)(g_kh + (size_t)b * NS * QKROW + h * DPAD);
    const char* kl_base = (const char*)(g_kl + (size_t)b * NS * QKROW + h * DPAD);
    const char* vh_base = (const char*)(g_vth + (size_t)(b * NH + h) * DPAD * SVT);
    const char* vl_base = (const char*)(g_vtl + (size_t)(b * NH + h) * DPAD * SVT);

    // ---- stage Q (hi only) via K buffer, build register fragments ----
    for (int i = tid; i < 768; i += 128) {
        int row = i / 12, ch = i % 12;
        int tok = q0 + row; if (tok > NS - 1) tok = NS - 1;
        size_t gb = (size_t)tok * (QKROW * 2) + ch * 16;
        cp16(smemu + OFF_KH + row * KSTB + ch * 16, qh_base + gb);
    }
    CP_COMMIT(); CP_WAIT(0);
    __syncthreads();

    const uint32_t aoffQ = (uint32_t)((wm + ((lane >> 3) & 1) * 8 + (lane & 7)) * KSTB
                                      + (lane >> 4) * 16);
    uint32_t qhf[6][4];
#pragma unroll
    for (int ks = 0; ks < 6; ks++)
        ldsm_x4(qhf[ks], smemu + OFF_KH + aoffQ + ks * 32);
    __syncthreads();

    float acc_o[11][4];
#pragma unroll
    for (int nt = 0; nt < 11; nt++)
#pragma unroll
        for (int j = 0; j < 4; j++) acc_o[nt][j] = 0.f;
    float mrun[2] = {-INFINITY, -INFINITY};
    float lrun[2] = {0.f, 0.f};

    const float scale = 0.10660035817780521f;
    const uint32_t kboff = (uint32_t)((((lane >> 4) << 3) + (lane & 7)) * KSTB
                                      + ((lane >> 3) & 1) * 16);
    const uint32_t vboff = (uint32_t)((((lane >> 4) << 3) + (lane & 7)) * VSTB
                                      + ((lane >> 3) & 1) * 16);
    const uint32_t apoff = (uint32_t)((wm + ((lane >> 3) & 1) * 8 + (lane & 7)) * VSTB
                                      + (lane >> 4) * 16);
    const int colb = (lane & 3) * 2;
    const int prow_lo = wm + (lane >> 2);

#pragma unroll 1
    for (int kt = 0; kt < 17; kt++) {
        const int k0 = kt * 64;

        // load K hi+lo and V^T hi+lo
        for (int i = tid; i < 768; i += 128) {
            int rk = i / 12, ck = i % 12;
            int tok = k0 + rk; if (tok > NS - 1) tok = NS - 1;
            size_t gk = (size_t)tok * (QKROW * 2) + ck * 16;
            cp16(smemu + OFF_KH + rk * KSTB + ck * 16, kh_base + gk);
            cp16(smemu + OFF_KL + rk * KSTB + ck * 16, kl_base + gk);
            int rv = i / 8, cv = i % 8;
            size_t gv = (size_t)rv * (SVT * 2) + k0 * 2 + cv * 16;
            cp16(smemu + OFF_VH + rv * VSTB + cv * 16, vh_base + gv);
            cp16(smemu + OFF_VL + rv * VSTB + cv * 16, vl_base + gv);
        }
        CP_COMMIT(); CP_WAIT(0);
        __syncthreads();

        // ---- S = Q K^T (2-term on K) ----
        float sacc[8][4];
#pragma unroll
        for (int nt = 0; nt < 8; nt++)
#pragma unroll
            for (int j = 0; j < 4; j++) sacc[nt][j] = 0.f;

#pragma unroll
        for (int ks = 0; ks < 6; ks++) {
            uint32_t kbh[16], kbl[16];
#pragma unroll
            for (int j = 0; j < 4; j++) {
                ldsm_x4(&kbh[j * 4], smemu + OFF_KH + kboff + j * 16 * KSTB + ks * 32);
                ldsm_x4(&kbl[j * 4], smemu + OFF_KL + kboff + j * 16 * KSTB + ks * 32);
            }
#pragma unroll
            for (int nt = 0; nt < 8; nt++) {
                mma_f16(sacc[nt], qhf[ks], &kbh[nt * 2]);
                mma_f16(sacc[nt], qhf[ks], &kbl[nt * 2]);
            }
        }

#pragma unroll
        for (int nt = 0; nt < 8; nt++)
#pragma unroll
            for (int j = 0; j < 4; j++) sacc[nt][j] *= scale;
        if (k0 + 64 > NS) {
#pragma unroll
            for (int nt = 0; nt < 8; nt++)
#pragma unroll
                for (int j = 0; j < 4; j++) {
                    int col = k0 + nt * 8 + colb + (j & 1);
                    if (col >= NS) sacc[nt][j] = -INFINITY;
                }
        }

        // ---- online softmax ----
        float ml0 = -INFINITY, ml1 = -INFINITY;
#pragma unroll
        for (int nt = 0; nt < 8; nt++) {
            ml0 = fmaxf(ml0, fmaxf(sacc[nt][0], sacc[nt][1]));
            ml1 = fmaxf(ml1, fmaxf(sacc[nt][2], sacc[nt][3]));
        }
        ml0 = fmaxf(ml0, __shfl_xor_sync(0xffffffffu, ml0, 1));
        ml0 = fmaxf(ml0, __shfl_xor_sync(0xffffffffu, ml0, 2));
        ml1 = fmaxf(ml1, __shfl_xor_sync(0xffffffffu, ml1, 1));
        ml1 = fmaxf(ml1, __shfl_xor_sync(0xffffffffu, ml1, 2));

        float mn0 = fmaxf(mrun[0], ml0), mn1 = fmaxf(mrun[1], ml1);
        float al0 = __expf(mrun[0] - mn0), al1 = __expf(mrun[1] - mn1);
        mrun[0] = mn0; mrun[1] = mn1;

        float rs0 = 0.f, rs1 = 0.f;
#pragma unroll
        for (int nt = 0; nt < 8; nt++) {
            float p00 = __expf(sacc[nt][0] - mn0);
            float p01 = __expf(sacc[nt][1] - mn0);
            float p10 = __expf(sacc[nt][2] - mn1);
            float p11 = __expf(sacc[nt][3] - mn1);
            rs0 += p00 + p01;
            rs1 += p10 + p11;
            uint32_t po = (uint32_t)(prow_lo * VSTB + (nt * 8 + colb) * 2);
            *(__half2*)(sm + OFF_PH + po) = __floats2half2_rn(p00, p01);
            *(__half2*)(sm + OFF_PH + po + 8 * VSTB) = __floats2half2_rn(p10, p11);
        }
        rs0 += __shfl_xor_sync(0xffffffffu, rs0, 1);
        rs0 += __shfl_xor_sync(0xffffffffu, rs0, 2);
        rs1 += __shfl_xor_sync(0xffffffffu, rs1, 1);
        rs1 += __shfl_xor_sync(0xffffffffu, rs1, 2);
        lrun[0] = lrun[0] * al0 + rs0;
        lrun[1] = lrun[1] * al1 + rs1;

#pragma unroll
        for (int nt = 0; nt < 11; nt++) {
            acc_o[nt][0] *= al0; acc_o[nt][1] *= al0;
            acc_o[nt][2] *= al1; acc_o[nt][3] *= al1;
        }
        __syncwarp();

        // ---- O += P V (2-term on V) ----
#pragma unroll
        for (int ks = 0; ks < 4; ks++) {
            uint32_t aph[4];
            ldsm_x4(aph, smemu + OFF_PH + apoff + ks * 32);
            uint32_t vbh[24], vbl[24];
#pragma unroll
            for (int j = 0; j < 6; j++) {
                ldsm_x4(&vbh[j * 4], smemu + OFF_VH + vboff + j * 16 * VSTB + ks * 32);
                ldsm_x4(&vbl[j * 4], smemu + OFF_VL + vboff + j * 16 * VSTB + ks * 32);
            }
#pragma unroll
            for (int nt = 0; nt < 11; nt++) {
                mma_f16(acc_o[nt], aph, &vbh[nt * 2]);
                mma_f16(acc_o[nt], aph, &vbl[nt * 2]);
            }
        }
        __syncthreads();
    }

    // ---- epilogue: ctx as fp16 hi (feeds Wo GEMM) ----
    const float inv0 = 1.f / lrun[0];
    const float inv1 = 1.f / lrun[1];
    const int gq0 = q0 + wm + (lane >> 2);
    const int gq1 = gq0 + 8;
    const size_t ob = (size_t)b * NS * NE + (size_t)h * ND;
#pragma unroll
    for (int nt = 0; nt < 11; nt++) {
        int col = nt * 8 + colb;
        if (gq0 < NS) {
            size_t off = ob + (size_t)gq0 * NE + col;
            *(__half2*)(g_ch + off) =
                __floats2half2_rn(acc_o[nt][0] * inv0, acc_o[nt][1] * inv0);
        }
        if (gq1 < NS) {
            size_t off = ob + (size_t)gq1 * NE + col;
            *(__half2*)(g_ch + off) =
                __floats2half2_rn(acc_o[nt][2] * inv1, acc_o[nt][3] * inv1);
        }
    }
}

// ---------------------------------------------------------------------------
// Launch
// ---------------------------------------------------------------------------
extern "C" void kernel_launch(void* const* d_in, const int* in_sizes, int n_in,
                              void* d_out, int out_size)
{
    const float* hidden = (const float*)d_in[0];
    const float* fcos   = (const float*)d_in[1];
    const float* fsin   = (const float*)d_in[2];
    const float* Wq     = (const float*)d_in[3];
    const float* bq     = (const float*)d_in[4];
    const float* Wk     = (const float*)d_in[5];
    const float* bk     = (const float*)d_in[6];
    const float* Wv     = (const float*)d_in[7];
    const float* bv     = (const float*)d_in[8];
    const float* Wo     = (const float*)d_in[9];
    const float* bo     = (const float*)d_in[10];
    float* out = (float*)d_out;

    __half *ah, *wh, *wl;
    cudaGetSymbolAddress((void**)&ah, g_ah);
    cudaGetSymbolAddress((void**)&wh, g_wh);
    cudaGetSymbolAddress((void**)&wl, g_wl);

    static int smem_set = 0;
    if (!smem_set) {
        cudaFuncSetAttribute(gemm_qkv_kernel,
                             cudaFuncAttributeMaxDynamicSharedMemorySize, GEMM_SMEM);
        cudaFuncSetAttribute(gemm_wo_kernel,
                             cudaFuncAttributeMaxDynamicSharedMemorySize, GEMM_SMEM);
        cudaFuncSetAttribute(attn_hmma_kernel,
                             cudaFuncAttributeMaxDynamicSharedMemorySize, ATT_SMEM);
        smem_set = 1;
    }

    // ---- prep ----
    const int nA4 = NM * NE / 4;
    const int nW4 = EE / 4;
    tohalf_kernel<<<(nA4 + 255) / 256, 256>>>(hidden, ah, nA4);
    dim3 sgrid((nW4 + 255) / 256, 4);
    split4_kernel<<<sgrid, 256>>>(Wq, Wk, Wv, Wo, wh, wl, nW4);

    // ---- fused QKV projections (+RoPE, +V transpose) ----
    dim3 qkv_grid(33, (NM + 127) / 128);   // (33, 65)
    gemm_qkv_kernel<<<qkv_grid, 256, GEMM_SMEM>>>(bq, bk, bv, fcos, fsin);

    // ---- attention ----
    dim3 attn_grid(17, NH, NB);
    attn_hmma_kernel<<<attn_grid, 128, ATT_SMEM>>>();

    // ---- output projection ----
    dim3 wo_grid(11, (NM + 127) / 128);
    gemm_wo_kernel<<<wo_grid, 256, GEMM_SMEM>>>(bo, out);
}

// round 10
// speedup vs baseline: 2.3435x; 1.5463x over previous
#include <cuda_runtime.h>
#include <cuda_fp16.h>
#include <math.h>
#include <stdint.h>

#define NB 8
#define NS 1025
#define NE 1408
#define NH 16
#define ND 88
#define NM (NB*NS)      // 8200
#define DPAD 96
#define QKROW (NH*DPAD) // 1536
#define SVT 1088        // padded token dim for V^T
#define EE  (NE*NE)

// Persistent scratch (zero-initialized; padding regions stay zero).
static __device__ __half g_ah[(size_t)NM * NE];          // hidden fp16
static __device__ __half g_wh[(size_t)4 * EE];           // weights fp16
static __device__ __half g_ch[(size_t)NM * NE];          // ctx fp16
static __device__ __half g_qh[(size_t)NM * QKROW];       // q (rope) fp16
static __device__ __half g_kh[(size_t)NM * QKROW];       // k (rope) fp16
static __device__ __half g_vth[(size_t)NB * NH * DPAD * SVT];  // V^T fp16

// ===========================================================================
// Helpers
// ===========================================================================
__device__ __forceinline__ uint32_t smem_to_u32(const void* p) {
    uint32_t a;
    asm("{ .reg .u64 t; cvta.to.shared.u64 t, %1; cvt.u32.u64 %0, t; }"
        : "=r"(a) : "l"(p));
    return a;
}
__device__ __forceinline__ void ldsm_x4(uint32_t* r, uint32_t addr) {
    asm volatile("ldmatrix.sync.aligned.m8n8.x4.shared.b16 {%0,%1,%2,%3}, [%4];"
                 : "=r"(r[0]), "=r"(r[1]), "=r"(r[2]), "=r"(r[3]) : "r"(addr));
}
__device__ __forceinline__ void mma_f16(float* c, const uint32_t* a,
                                        const uint32_t* b) {
    asm volatile(
        "mma.sync.aligned.m16n8k16.row.col.f32.f16.f16.f32 "
        "{%0,%1,%2,%3}, {%4,%5,%6,%7}, {%8,%9}, {%0,%1,%2,%3};"
        : "+f"(c[0]), "+f"(c[1]), "+f"(c[2]), "+f"(c[3])
        : "r"(a[0]), "r"(a[1]), "r"(a[2]), "r"(a[3]), "r"(b[0]), "r"(b[1]));
}
__device__ __forceinline__ void cp16(uint32_t dst, const void* src) {
    asm volatile("cp.async.cg.shared.global [%0], [%1], 16;"
                 :: "r"(dst), "l"(__cvta_generic_to_global(src)));
}
#define CP_COMMIT() asm volatile("cp.async.commit_group;" ::: "memory")
#define CP_WAIT(n)  asm volatile("cp.async.wait_group %0;" :: "n"(n) : "memory")

// ===========================================================================
// Prep kernels (fp16 convert)
// ===========================================================================
__global__ void tohalf_kernel(const float* __restrict__ in,
                              __half* __restrict__ hi, int n4)
{
    int i = blockIdx.x * blockDim.x + threadIdx.x;
    if (i >= n4) return;
    float4 x = ((const float4*)in)[i];
    union { __half2 h2[2]; uint2 u; } H;
    H.h2[0] = __floats2half2_rn(x.x, x.y);
    H.h2[1] = __floats2half2_rn(x.z, x.w);
    ((uint2*)hi)[i] = H.u;
}

__global__ void tohalf4_kernel(const float* __restrict__ w0,
                               const float* __restrict__ w1,
                               const float* __restrict__ w2,
                               const float* __restrict__ w3,
                               __half* __restrict__ hi, int n4)
{
    int i = blockIdx.x * blockDim.x + threadIdx.x;
    if (i >= n4) return;
    const int g = blockIdx.y;
    const float* in = (g == 0) ? w0 : (g == 1) ? w1 : (g == 2) ? w2 : w3;
    float4 x = ((const float4*)in)[i];
    union { __half2 h2[2]; uint2 u; } H;
    H.h2[0] = __floats2half2_rn(x.x, x.y);
    H.h2[1] = __floats2half2_rn(x.z, x.w);
    ((uint2*)hi)[(size_t)g * (EE / 4) + i] = H.u;
}

// ===========================================================================
// HMMA GEMM, fp16 single-term: C = A * W^T + bias
// CTA 128x128, 8 warps (2x4), warp tile 64x32, BK=32, cp.async 3-stage.
// ===========================================================================
#define GK      NE
#define BKC     32
#define NCHUNK  (GK / BKC)    // 44
#define SROW    40
#define SROWB   (SROW * 2)
#define MAT_BYTES   (128 * SROWB)          // 10240
#define STAGE_BYTES (2 * MAT_BYTES)        // 20480 (A, W)
#define GEMM_SMEM   (3 * STAGE_BYTES)      // 61440

#define GEMM_PROLOG \
    extern __shared__ char sm[]; \
    const uint32_t smemu = smem_to_u32(sm); \
    const int tid  = threadIdx.x; \
    const int wid  = tid >> 5; \
    const int lane = tid & 31; \
    const int bm = blockIdx.y * 128; \
    const int wm = (wid >> 2) * 64; \
    const int wn = (wid & 3) * 32; \
    int rowL[2], chL[2], gaL[2]; \
    _Pragma("unroll") \
    for (int i = 0; i < 2; i++) { \
        int slot = tid + i * 256; \
        rowL[i] = slot >> 2; \
        chL[i]  = slot & 3; \
        int ga = bm + rowL[i]; \
        gaL[i] = (ga < NM) ? ga : (NM - 1); \
    } \
    const uint32_t aoff = \
        (uint32_t)((wm + ((lane >> 3) & 1) * 8 + (lane & 7)) * SROWB \
                   + (lane >> 4) * 16); \
    const uint32_t boff = \
        (uint32_t)((wn + ((lane >> 4) << 3) + (lane & 7)) * SROWB \
                   + ((lane >> 3) & 1) * 16); \
    float acc[4][4][4]; \
    _Pragma("unroll") \
    for (int mi = 0; mi < 4; mi++) \
        _Pragma("unroll") \
        for (int ni = 0; ni < 4; ni++) \
            _Pragma("unroll") \
            for (int j = 0; j < 4; j++) acc[mi][ni][j] = 0.f;

#define GEMM_LOAD(c_) do { \
    const int k0_ = (c_) * BKC; \
    const uint32_t sb_ = smemu + ((c_) % 3) * STAGE_BYTES; \
    _Pragma("unroll") \
    for (int i_ = 0; i_ < 2; i_++) { \
        uint32_t so_ = (uint32_t)(rowL[i_] * SROWB + chL[i_] * 16); \
        size_t ao_ = ((size_t)gaL[i_] * GK + k0_ + chL[i_] * 8) * 2; \
        cp16(sb_ + so_, (const char*)Ah + ao_); \
        size_t bo_ = ((size_t)(bn + rowL[i_]) * GK + k0_ + chL[i_] * 8) * 2; \
        cp16(sb_ + MAT_BYTES + so_, (const char*)Wh + bo_); \
    } \
} while (0)

#define GEMM_MAINLOOP \
    GEMM_LOAD(0); CP_COMMIT(); \
    GEMM_LOAD(1); CP_COMMIT(); \
    _Pragma("unroll 1") \
    for (int c = 0; c < NCHUNK; c++) { \
        if (c + 1 < NCHUNK) { CP_WAIT(1); } else { CP_WAIT(0); } \
        __syncthreads(); \
        if (c + 2 < NCHUNK) { GEMM_LOAD(c + 2); CP_COMMIT(); } \
        const uint32_t base = smemu + (uint32_t)((c % 3) * STAGE_BYTES); \
        const uint32_t aHi = base; \
        const uint32_t bHi = base + MAT_BYTES; \
        _Pragma("unroll") \
        for (int ks = 0; ks < 2; ks++) { \
            const uint32_t ksb = ks * 32; \
            uint32_t ah[16], bh[8]; \
            _Pragma("unroll") \
            for (int mi = 0; mi < 4; mi++) \
                ldsm_x4(&ah[mi * 4], aHi + aoff + mi * 16 * SROWB + ksb); \
            ldsm_x4(&bh[0], bHi + boff + ksb); \
            ldsm_x4(&bh[4], bHi + boff + 16 * SROWB + ksb); \
            _Pragma("unroll") \
            for (int mi = 0; mi < 4; mi++) \
                _Pragma("unroll") \
                for (int ni = 0; ni < 4; ni++) \
                    mma_f16(acc[mi][ni], &ah[mi * 4], &bh[ni * 2]); \
        } \
        __syncthreads(); \
    }

// Fused QKV GEMM: grid.x = 33 (g = bx/11): g0->Q(RoPE), g1->K(RoPE), g2->V^T
__global__ __launch_bounds__(256, 2) void gemm_qkv_kernel(
    const float* __restrict__ bq, const float* __restrict__ bk,
    const float* __restrict__ bv,
    const float* __restrict__ rcos, const float* __restrict__ rsin)
{
    const int g  = blockIdx.x / 11;
    const int bn = (blockIdx.x % 11) * 128;
    const __half* Ah = g_ah;
    const __half* Wh = g_wh + (size_t)g * EE;
    const float* bias = (g == 0) ? bq : (g == 1) ? bk : bv;

    GEMM_PROLOG
    GEMM_MAINLOOP

    const int r0 = bm + wm + (lane >> 2);
    const int c0 = bn + wn + (lane & 3) * 2;
#pragma unroll
    for (int mi = 0; mi < 4; mi++) {
#pragma unroll
        for (int nt = 0; nt < 4; nt++) {
            const int gc = c0 + nt * 8;
            const float bx = bias[gc], by = bias[gc + 1];
            const int hh = gc / ND;
            const int dd = gc - hh * ND;
#pragma unroll
            for (int h2i = 0; h2i < 2; h2i++) {
                const int gr = r0 + mi * 16 + h2i * 8;
                if (gr >= NM) continue;
                float xr = acc[mi][nt][2 * h2i + 0] + bx;
                float xi = acc[mi][nt][2 * h2i + 1] + by;
                if (g <= 1) {
                    const int st = gr % NS;
                    const float cc = rcos[st * (ND / 2) + (dd >> 1)];
                    const float ss = rsin[st * (ND / 2) + (dd >> 1)];
                    float orr = xr * cc - xi * ss;
                    float oii = xr * ss + xi * cc;
                    size_t off = (size_t)gr * QKROW + hh * DPAD + dd;
                    __half* dst = (g == 0) ? g_qh : g_kh;
                    *(__half2*)(dst + off) = __floats2half2_rn(orr, oii);
                } else {
                    const int bb = gr / NS;
                    const int st = gr - bb * NS;
                    size_t base2 = ((size_t)((bb * NH + hh) * DPAD) + dd) * SVT + st;
                    g_vth[base2]       = __float2half_rn(xr);
                    g_vth[base2 + SVT] = __float2half_rn(xi);
                }
            }
        }
    }
}

// Wo GEMM (fp32 out)
__global__ __launch_bounds__(256, 2) void gemm_wo_kernel(
    const float* __restrict__ bias, float* __restrict__ C)
{
    const int bn = blockIdx.x * 128;
    const __half* Ah = g_ch;
    const __half* Wh = g_wh + (size_t)3 * EE;

    GEMM_PROLOG
    GEMM_MAINLOOP

    const int r0 = bm + wm + (lane >> 2);
    const int c0 = bn + wn + (lane & 3) * 2;
#pragma unroll
    for (int mi = 0; mi < 4; mi++) {
#pragma unroll
        for (int nt = 0; nt < 4; nt++) {
            const int gc = c0 + nt * 8;
            const float bx = bias[gc], by = bias[gc + 1];
#pragma unroll
            for (int h2i = 0; h2i < 2; h2i++) {
                const int gr = r0 + mi * 16 + h2i * 8;
                if (gr >= NM) continue;
                float xr = acc[mi][nt][2 * h2i + 0] + bx;
                float xi = acc[mi][nt][2 * h2i + 1] + by;
                *(float2*)(C + (size_t)gr * NE + gc) = make_float2(xr, xi);
            }
        }
    }
}

// ===========================================================================
// HMMA flash attention, fp16 single-term, K+V double-buffered.
// BQ=64, BK=64, 4 warps, 3 CTAs/SM.
// ===========================================================================
#define KSTB 208
#define VSTB 144
#define KVSTAGE_B 27136                  // 64*208 + 96*144
#define OFF_V_IN_STAGE 13312
#define OFF_PH (2 * KVSTAGE_B)           // 54272
#define ATT_SMEM (OFF_PH + 64 * VSTB)    // 63488

__global__ __launch_bounds__(128, 3) void attn_hmma_kernel()
{
    extern __shared__ char sm[];
    const uint32_t smemu = smem_to_u32(sm);
    const int tid  = threadIdx.x;
    const int wid  = tid >> 5;
    const int lane = tid & 31;
    const int wm   = wid * 16;

    const int qt = blockIdx.x, h = blockIdx.y, b = blockIdx.z;
    const int q0 = qt * 64;

    const char* qh_base = (const char*)(g_qh + (size_t)b * NS * QKROW + h * DPAD);
    const char* kh_base = (const char*)(g_kh + (size_t)b * NS * QKROW + h * DPAD);
    const char* vh_base = (const char*)(g_vth + (size_t)(b * NH + h) * DPAD * SVT);

    // ---- stage Q via stage-0 K buffer, build register fragments ----
    for (int i = tid; i < 768; i += 128) {
        int row = i / 12, ch = i % 12;
        int tok = q0 + row; if (tok > NS - 1) tok = NS - 1;
        cp16(smemu + row * KSTB + ch * 16,
             qh_base + (size_t)tok * (QKROW * 2) + ch * 16);
    }
    CP_COMMIT(); CP_WAIT(0);
    __syncthreads();

    const uint32_t aoffQ = (uint32_t)((wm + ((lane >> 3) & 1) * 8 + (lane & 7)) * KSTB
                                      + (lane >> 4) * 16);
    uint32_t qhf[6][4];
#pragma unroll
    for (int ks = 0; ks < 6; ks++)
        ldsm_x4(qhf[ks], smemu + aoffQ + ks * 32);
    __syncthreads();

    // ---- preload K+V (kt=0) into stage 0 ----
    for (int i = tid; i < 1536; i += 128) {
        if (i < 768) {
            int rk = i / 12, ck = i % 12;
            int tok = rk; if (tok > NS - 1) tok = NS - 1;
            cp16(smemu + rk * KSTB + ck * 16,
                 kh_base + (size_t)tok * (QKROW * 2) + ck * 16);
        } else {
            int j = i - 768;
            int rv = j / 8, cv = j % 8;
            cp16(smemu + OFF_V_IN_STAGE + rv * VSTB + cv * 16,
                 vh_base + (size_t)rv * (SVT * 2) + cv * 16);
        }
    }
    CP_COMMIT();

    float acc_o[11][4];
#pragma unroll
    for (int nt = 0; nt < 11; nt++)
#pragma unroll
        for (int j = 0; j < 4; j++) acc_o[nt][j] = 0.f;
    float mrun[2] = {-INFINITY, -INFINITY};
    float lrun[2] = {0.f, 0.f};

    const float scale = 0.10660035817780521f;
    const uint32_t kboff = (uint32_t)((((lane >> 4) << 3) + (lane & 7)) * KSTB
                                      + ((lane >> 3) & 1) * 16);
    const uint32_t vboff = (uint32_t)((((lane >> 4) << 3) + (lane & 7)) * VSTB
                                      + ((lane >> 3) & 1) * 16);
    const uint32_t apoff = (uint32_t)((wm + ((lane >> 3) & 1) * 8 + (lane & 7)) * VSTB
                                      + (lane >> 4) * 16);
    const int colb = (lane & 3) * 2;
    const int prow_lo = wm + (lane >> 2);

#pragma unroll 1
    for (int kt = 0; kt < 17; kt++) {
        const int k0 = kt * 64;

        // prefetch K+V (kt+1) into the other stage
        if (kt + 1 < 17) {
            const uint32_t snx = smemu + ((kt + 1) & 1) * KVSTAGE_B;
            const int kn0 = (kt + 1) * 64;
            for (int i = tid; i < 1536; i += 128) {
                if (i < 768) {
                    int rk = i / 12, ck = i % 12;
                    int tok = kn0 + rk; if (tok > NS - 1) tok = NS - 1;
                    cp16(snx + rk * KSTB + ck * 16,
                         kh_base + (size_t)tok * (QKROW * 2) + ck * 16);
                } else {
                    int j = i - 768;
                    int rv = j / 8, cv = j % 8;
                    cp16(snx + OFF_V_IN_STAGE + rv * VSTB + cv * 16,
                         vh_base + (size_t)rv * (SVT * 2) + kn0 * 2 + cv * 16);
                }
            }
            CP_COMMIT(); CP_WAIT(1);
        } else {
            CP_WAIT(0);
        }
        __syncthreads();

        const uint32_t scur = smemu + (kt & 1) * KVSTAGE_B;

        // ---- S = Q K^T ----
        float sacc[8][4];
#pragma unroll
        for (int nt = 0; nt < 8; nt++)
#pragma unroll
            for (int j = 0; j < 4; j++) sacc[nt][j] = 0.f;

#pragma unroll
        for (int ks = 0; ks < 6; ks++) {
            uint32_t kbh[16];
#pragma unroll
            for (int j = 0; j < 4; j++)
                ldsm_x4(&kbh[j * 4], scur + kboff + j * 16 * KSTB + ks * 32);
#pragma unroll
            for (int nt = 0; nt < 8; nt++)
                mma_f16(sacc[nt], qhf[ks], &kbh[nt * 2]);
        }

#pragma unroll
        for (int nt = 0; nt < 8; nt++)
#pragma unroll
            for (int j = 0; j < 4; j++) sacc[nt][j] *= scale;
        if (k0 + 64 > NS) {
#pragma unroll
            for (int nt = 0; nt < 8; nt++)
#pragma unroll
                for (int j = 0; j < 4; j++) {
                    int col = k0 + nt * 8 + colb + (j & 1);
                    if (col >= NS) sacc[nt][j] = -INFINITY;
                }
        }

        // ---- online softmax ----
        float ml0 = -INFINITY, ml1 = -INFINITY;
#pragma unroll
        for (int nt = 0; nt < 8; nt++) {
            ml0 = fmaxf(ml0, fmaxf(sacc[nt][0], sacc[nt][1]));
            ml1 = fmaxf(ml1, fmaxf(sacc[nt][2], sacc[nt][3]));
        }
        ml0 = fmaxf(ml0, __shfl_xor_sync(0xffffffffu, ml0, 1));
        ml0 = fmaxf(ml0, __shfl_xor_sync(0xffffffffu, ml0, 2));
        ml1 = fmaxf(ml1, __shfl_xor_sync(0xffffffffu, ml1, 1));
        ml1 = fmaxf(ml1, __shfl_xor_sync(0xffffffffu, ml1, 2));

        float mn0 = fmaxf(mrun[0], ml0), mn1 = fmaxf(mrun[1], ml1);
        float al0 = __expf(mrun[0] - mn0), al1 = __expf(mrun[1] - mn1);
        mrun[0] = mn0; mrun[1] = mn1;

        float rs0 = 0.f, rs1 = 0.f;
#pragma unroll
        for (int nt = 0; nt < 8; nt++) {
            float p00 = __expf(sacc[nt][0] - mn0);
            float p01 = __expf(sacc[nt][1] - mn0);
            float p10 = __expf(sacc[nt][2] - mn1);
            float p11 = __expf(sacc[nt][3] - mn1);
            rs0 += p00 + p01;
            rs1 += p10 + p11;
            uint32_t po = (uint32_t)(prow_lo * VSTB + (nt * 8 + colb) * 2);
            *(__half2*)(sm + OFF_PH + po) = __floats2half2_rn(p00, p01);
            *(__half2*)(sm + OFF_PH + po + 8 * VSTB) = __floats2half2_rn(p10, p11);
        }
        rs0 += __shfl_xor_sync(0xffffffffu, rs0, 1);
        rs0 += __shfl_xor_sync(0xffffffffu, rs0, 2);
        rs1 += __shfl_xor_sync(0xffffffffu, rs1, 1);
        rs1 += __shfl_xor_sync(0xffffffffu, rs1, 2);
        lrun[0] = lrun[0] * al0 + rs0;
        lrun[1] = lrun[1] * al1 + rs1;

#pragma unroll
        for (int nt = 0; nt < 11; nt++) {
            acc_o[nt][0] *= al0; acc_o[nt][1] *= al0;
            acc_o[nt][2] *= al1; acc_o[nt][3] *= al1;
        }
        __syncwarp();   // P rows are per-warp private; only warp-local ordering needed

        // ---- O += P V ----
#pragma unroll
        for (int ks = 0; ks < 4; ks++) {
            uint32_t aph[4];
            ldsm_x4(aph, smemu + OFF_PH + apoff + ks * 32);
            uint32_t vbh[24];
#pragma unroll
            for (int j = 0; j < 6; j++)
                ldsm_x4(&vbh[j * 4],
                        scur + OFF_V_IN_STAGE + vboff + j * 16 * VSTB + ks * 32);
#pragma unroll
            for (int nt = 0; nt < 11; nt++)
                mma_f16(acc_o[nt], aph, &vbh[nt * 2]);
        }
        __syncthreads();   // protect current KV stage + P before next iteration
    }

    // ---- epilogue: ctx as fp16 (feeds Wo GEMM) ----
    const float inv0 = 1.f / lrun[0];
    const float inv1 = 1.f / lrun[1];
    const int gq0 = q0 + wm + (lane >> 2);
    const int gq1 = gq0 + 8;
    const size_t ob = (size_t)b * NS * NE + (size_t)h * ND;
#pragma unroll
    for (int nt = 0; nt < 11; nt++) {
        int col = nt * 8 + colb;
        if (gq0 < NS) {
            *(__half2*)(g_ch + ob + (size_t)gq0 * NE + col) =
                __floats2half2_rn(acc_o[nt][0] * inv0, acc_o[nt][1] * inv0);
        }
        if (gq1 < NS) {
            *(__half2*)(g_ch + ob + (size_t)gq1 * NE + col) =
                __floats2half2_rn(acc_o[nt][2] * inv1, acc_o[nt][3] * inv1);
        }
    }
}

// ---------------------------------------------------------------------------
// Launch
// ---------------------------------------------------------------------------
extern "C" void kernel_launch(void* const* d_in, const int* in_sizes, int n_in,
                              void* d_out, int out_size)
{
    const float* hidden = (const float*)d_in[0];
    const float* fcos   = (const float*)d_in[1];
    const float* fsin   = (const float*)d_in[2];
    const float* Wq     = (const float*)d_in[3];
    const float* bq     = (const float*)d_in[4];
    const float* Wk     = (const float*)d_in[5];
    const float* bk     = (const float*)d_in[6];
    const float* Wv     = (const float*)d_in[7];
    const float* bv     = (const float*)d_in[8];
    const float* Wo     = (const float*)d_in[9];
    const float* bo     = (const float*)d_in[10];
    float* out = (float*)d_out;

    __half *ah, *wh;
    cudaGetSymbolAddress((void**)&ah, g_ah);
    cudaGetSymbolAddress((void**)&wh, g_wh);

    static int smem_set = 0;
    if (!smem_set) {
        cudaFuncSetAttribute(gemm_qkv_kernel,
                             cudaFuncAttributeMaxDynamicSharedMemorySize, GEMM_SMEM);
        cudaFuncSetAttribute(gemm_wo_kernel,
                             cudaFuncAttributeMaxDynamicSharedMemorySize, GEMM_SMEM);
        cudaFuncSetAttribute(attn_hmma_kernel,
                             cudaFuncAttributeMaxDynamicSharedMemorySize, ATT_SMEM);
        smem_set = 1;
    }

    // ---- prep ----
    const int nA4 = NM * NE / 4;
    const int nW4 = EE / 4;
    tohalf_kernel<<<(nA4 + 255) / 256, 256>>>(hidden, ah, nA4);
    dim3 sgrid((nW4 + 255) / 256, 4);
    tohalf4_kernel<<<sgrid, 256>>>(Wq, Wk, Wv, Wo, wh, nW4);

    // ---- fused QKV projections (+RoPE, +V transpose) ----
    dim3 qkv_grid(33, (NM + 127) / 128);   // (33, 65)
    gemm_qkv_kernel<<<qkv_grid, 256, GEMM_SMEM>>>(bq, bk, bv, fcos, fsin);

    // ---- attention ----
    dim3 attn_grid(17, NH, NB);
    attn_hmma_kernel<<<attn_grid, 128, ATT_SMEM>>>();

    // ---- output projection ----
    dim3 wo_grid(11, (NM + 127) / 128);
    gemm_wo_kernel<<<wo_grid, 256, GEMM_SMEM>>>(bo, out);
}